// round 4
// baseline (speedup 1.0000x reference)
#include <cuda_runtime.h>
#include <cstdint>
#include <cstddef>

// ScalarWaveletRecombiner: out[n,o] = W2[o]·silu(W1[o]·x[n] + b1[o]) + b2[o]
// x:[NC,64] W1:[32,128,64] b1:[32,128] W2:[32,128] b2:[32] -> out:[NC,32]
//
// Fused tf32 mma.sync kernel:
//   grid = (NC/256, 16); block = 512 threads (16 warps, 16 rows each, 2 MLPs/block)
//   GEMM1 via mma.m16n8k8.tf32 (RNA-converted operands, fp32 accum),
//   epilogue (bias + silu + W2 reduction) fused in registers + shfl.

#define KDIM 64
#define HDIM 128
#define ODIM 32
#define OPB 2
#define ROWS_PER_BLOCK 256
#define THREADS 512

// smem layout (bytes)
#define WS_OFF   0                      // tf32 W1, B-fragment order: [2][8][8][128] u32 = 65536
#define XS_OFF   65536                  // x tile [256][68] f32 = 69632
#define B1_OFF   135168                 // [2][128] f32
#define W2_OFF   136192                 // [2][128] f32
#define B2_OFF   137216                 // [2] f32
#define SMEM_BYTES 137232

__device__ __forceinline__ unsigned f2tf32(float f) {
    unsigned r;
    asm("cvt.rna.tf32.f32 %0, %1;" : "=r"(r) : "f"(f));
    return r;
}

__device__ __forceinline__ void mma_tf32(float* c, const unsigned* a, unsigned b0, unsigned b1) {
    asm volatile(
        "mma.sync.aligned.m16n8k8.row.col.f32.tf32.tf32.f32 "
        "{%0,%1,%2,%3},{%4,%5,%6,%7},{%8,%9},{%0,%1,%2,%3};"
        : "+f"(c[0]), "+f"(c[1]), "+f"(c[2]), "+f"(c[3])
        : "r"(a[0]), "r"(a[1]), "r"(a[2]), "r"(a[3]), "r"(b0), "r"(b1));
}

__device__ __forceinline__ float silu_f(float v) {
    return v * (1.0f / (1.0f + __expf(-v)));
}

__global__ __launch_bounds__(THREADS, 1)
void swr_kernel(const float* __restrict__ x, const float* __restrict__ W1,
                const float* __restrict__ b1, const float* __restrict__ W2,
                const float* __restrict__ b2, float* __restrict__ out, int NC)
{
    extern __shared__ char smem[];
    unsigned* ws = (unsigned*)(smem + WS_OFF);
    float*    xs = (float*)(smem + XS_OFF);
    float*   b1s = (float*)(smem + B1_OFF);
    float*   w2s = (float*)(smem + W2_OFF);
    float*   b2s = (float*)(smem + B2_OFF);

    const int tid = threadIdx.x;
    const int R0  = blockIdx.x * ROWS_PER_BLOCK;
    const int o0  = blockIdx.y * OPB;

    // ---- stage x tile: [256][64] -> xs row stride 68 (conflict-free A loads) ----
    for (int idx = tid; idx < ROWS_PER_BLOCK * (KDIM / 4); idx += THREADS) {
        int r  = idx >> 4;
        int c4 = (idx & 15) << 2;
        float4 v = *(const float4*)(x + (size_t)(R0 + r) * KDIM + c4);
        *(float4*)(xs + r * 68 + c4) = v;
    }

    // ---- stage W1 pre-swizzled into mma B-fragment order, tf32 ----
    // ws[((ol*8+kk)*8+np)*128 + lane*4 + j]:
    //   j0 = b0(n=2np), j1 = b1(n=2np), j2 = b0(n=2np+1), j3 = b1(n=2np+1)
    //   b0: B[k=kk*8+tig][n] ; b1: B[k=kk*8+tig+4][n] ; B[k][n] = W1[o][h=n*8+gid][k]
    for (int idx = tid; idx < OPB * 8 * 8 * 128; idx += THREADS) {
        int j  = idx & 3;
        int ln = (idx >> 2) & 31;
        int np = (idx >> 7) & 7;
        int kk = (idx >> 10) & 7;
        int ol = idx >> 13;
        int gid = ln >> 2, tg = ln & 3;
        int n = 2 * np + (j >> 1);
        int h = n * 8 + gid;
        int k = kk * 8 + tg + ((j & 1) << 2);
        ws[idx] = f2tf32(W1[((size_t)(o0 + ol) * HDIM + h) * KDIM + k]);
    }

    if (tid < OPB * HDIM) {
        int ol = tid >> 7, h = tid & 127;
        b1s[tid] = b1[(o0 + ol) * HDIM + h];
        w2s[tid] = W2[(o0 + ol) * HDIM + h];
    }
    if (tid < OPB) b2s[tid] = b2[o0 + tid];
    __syncthreads();

    const int w    = tid >> 5;
    const int lane = tid & 31;
    const int gID  = lane >> 2;
    const int tig  = lane & 3;
    const int rbase = w * 16;

    // ---- A fragments for all 8 k-steps (rows rbase+gID, rbase+gID+8) ----
    unsigned a[8][4];
    #pragma unroll
    for (int kk = 0; kk < 8; kk++) {
        int c0 = kk * 8 + tig;
        a[kk][0] = f2tf32(xs[(rbase + gID) * 68 + c0]);
        a[kk][1] = f2tf32(xs[(rbase + gID + 8) * 68 + c0]);
        a[kk][2] = f2tf32(xs[(rbase + gID) * 68 + c0 + 4]);
        a[kk][3] = f2tf32(xs[(rbase + gID + 8) * 68 + c0 + 4]);
    }

    #pragma unroll
    for (int ol = 0; ol < OPB; ol++) {
        float c[16][4];
        #pragma unroll
        for (int n = 0; n < 16; n++) {
            c[n][0] = 0.f; c[n][1] = 0.f; c[n][2] = 0.f; c[n][3] = 0.f;
        }

        #pragma unroll
        for (int kk = 0; kk < 8; kk++) {
            const uint4* wrow = (const uint4*)(ws + ((ol * 8 + kk) * 8) * 128);
            #pragma unroll
            for (int np = 0; np < 8; np++) {
                uint4 b = wrow[np * 32 + lane];
                mma_tf32(c[2 * np],     a[kk], b.x, b.y);
                mma_tf32(c[2 * np + 1], a[kk], b.z, b.w);
            }
        }

        // ---- fused epilogue: bias + silu + W2-weighted reduce over H ----
        float s0 = 0.f, s1 = 0.f;
        #pragma unroll
        for (int n = 0; n < 16; n++) {
            #pragma unroll
            for (int jj = 0; jj < 2; jj++) {
                int col = n * 8 + tig * 2 + jj;
                float bb = b1s[ol * 128 + col];
                float ww = w2s[ol * 128 + col];
                s0 += silu_f(c[n][jj]     + bb) * ww;
                s1 += silu_f(c[n][2 + jj] + bb) * ww;
            }
        }
        // reduce across the 4 threads sharing a row (tig = low 2 lane bits)
        s0 += __shfl_xor_sync(0xffffffffu, s0, 1);
        s0 += __shfl_xor_sync(0xffffffffu, s0, 2);
        s1 += __shfl_xor_sync(0xffffffffu, s1, 1);
        s1 += __shfl_xor_sync(0xffffffffu, s1, 2);

        if (tig == 0) {
            int row = R0 + rbase + gID;
            float bo = b2s[ol];
            out[(size_t)row * ODIM + (o0 + ol)]       = s0 + bo;
            out[(size_t)(row + 8) * ODIM + (o0 + ol)] = s1 + bo;
        }
    }
}

extern "C" void kernel_launch(void* const* d_in, const int* in_sizes, int n_in,
                              void* d_out, int out_size)
{
    const float* x  = (const float*)d_in[0];  // [NC, 64]
    const float* W1 = (const float*)d_in[1];  // [32, 128, 64]
    const float* b1 = (const float*)d_in[2];  // [32, 128]
    const float* W2 = (const float*)d_in[3];  // [32, 128]
    const float* b2 = (const float*)d_in[4];  // [32]
    float* out = (float*)d_out;               // [NC, 32]

    int NC = in_sizes[0] / KDIM;              // 131072

    cudaFuncSetAttribute(swr_kernel, cudaFuncAttributeMaxDynamicSharedMemorySize, SMEM_BYTES);

    dim3 grid(NC / ROWS_PER_BLOCK, ODIM / OPB);
    swr_kernel<<<grid, THREADS, SMEM_BYTES>>>(x, W1, b1, W2, b2, out, NC);
}

// round 6
// speedup vs baseline: 1.4828x; 1.4828x over previous
#include <cuda_runtime.h>
#include <cstdint>
#include <cstddef>

// ScalarWaveletRecombiner: out[n,o] = W2[o]·silu(W1[o]·x[n] + b1[o]) + b2[o]
// x:[NC,64] W1:[32,128,64] b1:[32,128] W2:[32,128] b2:[32] -> out:[NC,32]
//
// mma.sync.m16n8k8.tf32 kernel, v2:
//   grid (NC/256, 8); 512 threads = 16 warps, each m32 x n64 tile; 4 MLPs/CTA.
//   x pre-converted to tf32 in smem; W1 staged in B-fragment order (conflict-free).
//   Fused epilogue: bias + silu (ex2+rcp approx) + W2 reduction + coalesced store.

#define KDIM 64
#define HDIM 128
#define ODIM 32
#define OPB 4
#define ROWS 256
#define THREADS 512

// smem layout (bytes)
#define XS_OFF    0         // tf32 x tile [256][68] u32          = 69632
#define WS_OFF    69632     // tf32 W1 frags [4][8][8][128] u32   = 131072
#define BW_OFF    200704    // float2 (b1, w2) [4][128]           = 4096
#define PART_OFF  204800    // float [2][256]                     = 2048
#define OUTB_OFF  206848    // float4 [256]                       = 4096
#define B2_OFF    210944    // float [4]
#define SMEM_BYTES 210960

__device__ __forceinline__ unsigned f2tf32(float f) {
    unsigned r;
    asm("cvt.rna.tf32.f32 %0, %1;" : "=r"(r) : "f"(f));
    return r;
}

__device__ __forceinline__ void mma_tf32(float* c, const unsigned* a, unsigned b0, unsigned b1) {
    asm volatile(
        "mma.sync.aligned.m16n8k8.row.col.f32.tf32.tf32.f32 "
        "{%0,%1,%2,%3},{%4,%5,%6,%7},{%8,%9},{%0,%1,%2,%3};"
        : "+f"(c[0]), "+f"(c[1]), "+f"(c[2]), "+f"(c[3])
        : "r"(a[0]), "r"(a[1]), "r"(a[2]), "r"(a[3]), "r"(b0), "r"(b1));
}

__device__ __forceinline__ float silu_fast(float v) {
    // silu(v) = v / (1 + e^{-v});  e^{-v} = 2^{-v*log2(e)}
    float e, r;
    asm("ex2.approx.f32 %0, %1;" : "=f"(e) : "f"(v * -1.4426950408889634f));
    asm("rcp.approx.f32 %0, %1;" : "=f"(r) : "f"(1.0f + e));
    return v * r;
}

__global__ __launch_bounds__(THREADS, 1)
void swr_kernel(const float* __restrict__ x, const float* __restrict__ W1,
                const float* __restrict__ b1, const float* __restrict__ W2,
                const float* __restrict__ b2, float* __restrict__ out)
{
    extern __shared__ char sm[];
    unsigned* xs  = (unsigned*)(sm + XS_OFF);
    unsigned* ws  = (unsigned*)(sm + WS_OFF);
    float2*   bw  = (float2*)(sm + BW_OFF);
    float*    part = (float*)(sm + PART_OFF);
    float4*   outb = (float4*)(sm + OUTB_OFF);
    float*    b2s  = (float*)(sm + B2_OFF);

    const int tid = threadIdx.x;
    const int R0  = blockIdx.x * ROWS;
    const int o0  = blockIdx.y * OPB;

    // ---- stage x tile as tf32: [256][64] -> xs row stride 68 (conflict-free) ----
    for (int idx = tid; idx < ROWS * (KDIM / 4); idx += THREADS) {
        int r  = idx >> 4;
        int c4 = (idx & 15) << 2;
        float4 v = *(const float4*)(x + (size_t)(R0 + r) * KDIM + c4);
        uint4 u;
        u.x = f2tf32(v.x); u.y = f2tf32(v.y); u.z = f2tf32(v.z); u.w = f2tf32(v.w);
        *(uint4*)(xs + r * 68 + c4) = u;
    }

    // ---- stage W1 as tf32 in B-fragment order (conflict-free STS) ----
    // ws[((ol*8+kk)*8+npg)*128 + lane*4 + j]:
    //   n = 2*npg + (j>>1); h = n*8 + (lane>>2); k = kk*8 + (lane&3) + ((j&1)<<2)
    for (int idx = tid; idx < OPB * 8192; idx += THREADS) {
        int j   = idx & 3;
        int ln  = (idx >> 2) & 31;
        int npg = (idx >> 7) & 7;
        int kk  = (idx >> 10) & 7;
        int ol  = idx >> 13;
        int n = 2 * npg + (j >> 1);
        int h = n * 8 + (ln >> 2);
        int k = kk * 8 + (ln & 3) + ((j & 1) << 2);
        ws[idx] = f2tf32(W1[((size_t)(o0 + ol) * HDIM + h) * KDIM + k]);
    }

    if (tid < OPB * HDIM) {
        int ol = tid >> 7, h = tid & 127;
        bw[tid] = make_float2(b1[(o0 + ol) * HDIM + h], W2[(o0 + ol) * HDIM + h]);
    }
    if (tid < OPB) b2s[tid] = b2[o0 + tid];
    __syncthreads();

    const int w    = tid >> 5;
    const int lane = tid & 31;
    const int rg   = w >> 1;          // row-group 0..7 (32 rows each)
    const int cg   = w & 1;           // col-group 0..1 (64 H-cols each)
    const int gID  = lane >> 2;
    const int tig  = lane & 3;
    const int rw   = rg * 32;

    const unsigned* xrow = xs + (rw + gID) * 68;
    const uint4* wsv = (const uint4*)ws;

    #pragma unroll 1
    for (int ol = 0; ol < OPB; ++ol) {
        float c[2][8][4];
        #pragma unroll
        for (int n = 0; n < 8; ++n) {
            #pragma unroll
            for (int t = 0; t < 2; ++t) {
                c[t][n][0] = 0.f; c[t][n][1] = 0.f; c[t][n][2] = 0.f; c[t][n][3] = 0.f;
            }
        }

        const uint4* wb = wsv + ((ol * 8) * 8 + cg * 4) * 32 + lane;

        #pragma unroll
        for (int kk = 0; kk < 8; ++kk) {
            const int c0 = kk * 8 + tig;
            unsigned a0[4], a1[4];
            a0[0] = xrow[c0];            a0[1] = xrow[8 * 68 + c0];
            a0[2] = xrow[c0 + 4];        a0[3] = xrow[8 * 68 + c0 + 4];
            a1[0] = xrow[16 * 68 + c0];  a1[1] = xrow[24 * 68 + c0];
            a1[2] = xrow[16 * 68 + c0 + 4]; a1[3] = xrow[24 * 68 + c0 + 4];

            const uint4* wk = wb + kk * 256;   // advance 8 npg-rows of 32 uint4
            #pragma unroll
            for (int nl = 0; nl < 4; ++nl) {
                uint4 b = wk[nl * 32];
                mma_tf32(c[0][2 * nl],     a0, b.x, b.y);
                mma_tf32(c[0][2 * nl + 1], a0, b.z, b.w);
                mma_tf32(c[1][2 * nl],     a1, b.x, b.y);
                mma_tf32(c[1][2 * nl + 1], a1, b.z, b.w);
            }
        }

        // ---- fused epilogue: bias + silu + W2-weighted reduction over H ----
        float acc[2][2] = {{0.f, 0.f}, {0.f, 0.f}};
        const float2* bwp = bw + ol * HDIM + cg * 64 + tig * 2;
        #pragma unroll
        for (int n = 0; n < 8; ++n) {
            float4 q = *(const float4*)(bwp + n * 8);  // (b1[h0],w2[h0],b1[h1],w2[h1])
            #pragma unroll
            for (int t = 0; t < 2; ++t) {
                float v0 = c[t][n][0] + q.x;
                float v1 = c[t][n][1] + q.z;
                float v2 = c[t][n][2] + q.x;
                float v3 = c[t][n][3] + q.z;
                acc[t][0] = fmaf(silu_fast(v0), q.y, acc[t][0]);
                acc[t][0] = fmaf(silu_fast(v1), q.w, acc[t][0]);
                acc[t][1] = fmaf(silu_fast(v2), q.y, acc[t][1]);
                acc[t][1] = fmaf(silu_fast(v3), q.w, acc[t][1]);
            }
        }

        #pragma unroll
        for (int t = 0; t < 2; ++t) {
            #pragma unroll
            for (int r = 0; r < 2; ++r) {
                float s = acc[t][r];
                s += __shfl_xor_sync(0xffffffffu, s, 1);
                s += __shfl_xor_sync(0xffffffffu, s, 2);
                if (tig == 0)
                    part[cg * 256 + rw + t * 16 + r * 8 + gID] = s;
            }
        }
        __syncthreads();

        if (tid < 256) {
            float v = part[tid] + part[256 + tid] + b2s[ol];
            ((float*)outb)[tid * 4 + ol] = v;
        }
        __syncthreads();
    }

    // ---- coalesced-ish final store: out[R0+row][o0..o0+3] as float4 ----
    if (tid < 256) {
        *(float4*)(out + (size_t)(R0 + tid) * ODIM + o0) = outb[tid];
    }
}

extern "C" void kernel_launch(void* const* d_in, const int* in_sizes, int n_in,
                              void* d_out, int out_size)
{
    const float* x  = (const float*)d_in[0];  // [NC, 64]
    const float* W1 = (const float*)d_in[1];  // [32, 128, 64]
    const float* b1 = (const float*)d_in[2];  // [32, 128]
    const float* W2 = (const float*)d_in[3];  // [32, 128]
    const float* b2 = (const float*)d_in[4];  // [32]
    float* out = (float*)d_out;               // [NC, 32]

    const int NC = in_sizes[0] / KDIM;        // 131072

    cudaFuncSetAttribute(swr_kernel, cudaFuncAttributeMaxDynamicSharedMemorySize, SMEM_BYTES);

    dim3 grid(NC / ROWS, ODIM / OPB);         // (512, 8)
    swr_kernel<<<grid, THREADS, SMEM_BYTES>>>(x, W1, b1, W2, b2, out);
}

// round 7
// speedup vs baseline: 2.4872x; 1.6774x over previous
#include <cuda_runtime.h>
#include <cstdint>
#include <cstddef>

// ScalarWaveletRecombiner: out[n,o] = W2[o]·silu(W1[o]·x[n] + b1[o]) + b2[o]
// x:[NC,64] W1:[32,128,64] b1:[32,128] W2:[32,128] b2:[32] -> out:[NC,32]
//
// v3: mma.sync.m16n8k8.tf32 + ldmatrix fragment loads.
//   grid (NC/256, 8); 512 threads = 16 warps (m32 x n64 tiles); 4 MLPs/CTA.
//   x and W1 staged LINEARLY as tf32 (coalesced), XOR-swizzled 16B chunks;
//   fragments loaded with ldmatrix.x4 (tf32-as-b16 trick, conflict-free).
//   Epilogue: silu via 1x tanh.approx, W2 reduction, single final sync.

#define KDIM 64
#define HDIM 128
#define ODIM 32
#define OPB 4
#define ROWS 256
#define THREADS 512

// smem layout (bytes)
#define XS_OFF    0         // tf32 x   [256 rows][256B]   = 65536
#define WS_OFF    65536     // tf32 W1  [512 hrows][256B]  = 131072
#define BW_OFF    196608    // float2 (0.5*b1, w2) [4][128] = 4096
#define PART_OFF  200704    // float [8][256]               = 8192
#define SMEM_BYTES 208896

__device__ __forceinline__ unsigned f2tf32(float f) {
    unsigned r;
    asm("cvt.rna.tf32.f32 %0, %1;" : "=r"(r) : "f"(f));
    return r;
}

__device__ __forceinline__ uint32_t smem_u32(const void* p) {
    uint32_t a;
    asm("{ .reg .u64 t; cvta.to.shared.u64 t, %1; cvt.u32.u64 %0, t; }" : "=r"(a) : "l"(p));
    return a;
}

__device__ __forceinline__ void ldsm4(uint32_t addr, unsigned* r) {
    asm volatile("ldmatrix.sync.aligned.m8n8.x4.shared.b16 {%0,%1,%2,%3}, [%4];"
                 : "=r"(r[0]), "=r"(r[1]), "=r"(r[2]), "=r"(r[3]) : "r"(addr));
}

__device__ __forceinline__ void mma_tf32(float* c, const unsigned* a, unsigned b0, unsigned b1) {
    asm volatile(
        "mma.sync.aligned.m16n8k8.row.col.f32.tf32.tf32.f32 "
        "{%0,%1,%2,%3},{%4,%5,%6,%7},{%8,%9},{%0,%1,%2,%3};"
        : "+f"(c[0]), "+f"(c[1]), "+f"(c[2]), "+f"(c[3])
        : "r"(a[0]), "r"(a[1]), "r"(a[2]), "r"(a[3]), "r"(b0), "r"(b1));
}

__device__ __forceinline__ float tanh_ap(float x) {
    float t;
    asm("tanh.approx.f32 %0, %1;" : "=f"(t) : "f"(x));
    return t;
}

__global__ __launch_bounds__(THREADS, 1)
void swr_kernel(const float* __restrict__ x, const float* __restrict__ W1,
                const float* __restrict__ b1, const float* __restrict__ W2,
                const float* __restrict__ b2, float* __restrict__ out)
{
    extern __shared__ char sm[];
    float2* bw   = (float2*)(sm + BW_OFF);
    float*  part = (float*)(sm + PART_OFF);

    const int tid = threadIdx.x;
    const int R0  = blockIdx.x * ROWS;
    const int o0  = blockIdx.y * OPB;

    // ---- stage x: [256 rows][64 tf32], 16B chunk ch swizzled by (ch ^ (row&7)) ----
    #pragma unroll
    for (int i = 0; i < 8; i++) {
        int idx = tid + i * THREADS;             // 4096 chunks
        int r = idx >> 4, ch = idx & 15;
        float4 v = *(const float4*)(x + (size_t)(R0 + r) * KDIM + ch * 4);
        uint4 u;
        u.x = f2tf32(v.x); u.y = f2tf32(v.y); u.z = f2tf32(v.z); u.w = f2tf32(v.w);
        *(uint4*)(sm + XS_OFF + r * 256 + ((ch ^ (r & 7)) << 4)) = u;
    }

    // ---- stage W1: [4 o][128 h] rows x [64 tf32], same swizzle ----
    #pragma unroll
    for (int i = 0; i < 16; i++) {
        int idx = tid + i * THREADS;             // 8192 chunks
        int hrow = idx >> 4, ch = idx & 15;
        int ol = hrow >> 7, h = hrow & 127;
        float4 v = *(const float4*)(W1 + ((size_t)(o0 + ol) * HDIM + h) * KDIM + ch * 4);
        uint4 u;
        u.x = f2tf32(v.x); u.y = f2tf32(v.y); u.z = f2tf32(v.z); u.w = f2tf32(v.w);
        *(uint4*)(sm + WS_OFF + hrow * 256 + ((ch ^ (hrow & 7)) << 4)) = u;
    }

    // ---- stage (0.5*b1, w2) pairs ----
    {
        int ol = tid >> 7, h = tid & 127;
        bw[tid] = make_float2(0.5f * b1[(o0 + ol) * HDIM + h], W2[(o0 + ol) * HDIM + h]);
    }
    __syncthreads();

    const int w    = tid >> 5;
    const int lane = tid & 31;
    const int rg   = w >> 1;                 // row-group (32 rows)
    const int cg   = w & 1;                  // col-group (64 h)
    const int rw   = rg * 32;
    const int hb   = cg * 64;
    const int gid  = lane >> 2;
    const int tig  = lane & 3;

    // per-lane ldmatrix base addresses
    const uint32_t smb = smem_u32(sm);
    const int sub = lane & 7;
    const int s   = sub;                          // swizzle key (row&7 == lane&7 here)
    const int cA  = (lane >> 4) & 1;              // A: k-half bit
    const int rA8 = (lane >> 3) & 1;              // A: +8 rows bit
    const int cB  = (lane >> 3) & 1;              // B: k-half bit
    const int rB8 = (lane >> 4) & 1;              // B: +8 rows bit
    const uint32_t pA = smb + XS_OFF + (uint32_t)(rw + sub + rA8 * 8) * 256;
    const uint32_t pB = smb + WS_OFF + (uint32_t)(hb + sub + rB8 * 8) * 256;

    #pragma unroll 1
    for (int ol = 0; ol < OPB; ++ol) {
        float c[2][8][4];
        #pragma unroll
        for (int n = 0; n < 8; ++n)
            #pragma unroll
            for (int t = 0; t < 2; ++t) {
                c[t][n][0] = 0.f; c[t][n][1] = 0.f; c[t][n][2] = 0.f; c[t][n][3] = 0.f;
            }

        const uint32_t pBol = pB + (uint32_t)ol * 32768;

        #pragma unroll
        for (int kk = 0; kk < 8; ++kk) {
            const uint32_t swA = (uint32_t)(((2 * kk + cA) ^ s) << 4);
            const uint32_t swB = (uint32_t)(((2 * kk + cB) ^ s) << 4);

            unsigned a0[4], a1[4];
            ldsm4(pA + swA, a0);                  // rows rw+0..15
            ldsm4(pA + 4096 + swA, a1);           // rows rw+16..31

            #pragma unroll
            for (int t = 0; t < 4; ++t) {
                unsigned b[4];                    // [ng 2t: b0,b1][ng 2t+1: b0,b1]
                ldsm4(pBol + (uint32_t)t * 4096 + swB, b);
                mma_tf32(c[0][2 * t],     a0, b[0], b[1]);
                mma_tf32(c[0][2 * t + 1], a0, b[2], b[3]);
                mma_tf32(c[1][2 * t],     a1, b[0], b[1]);
                mma_tf32(c[1][2 * t + 1], a1, b[2], b[3]);
            }
        }

        // ---- fused epilogue: silu (tanh.approx) + W2 reduction ----
        float acc[2][2] = {{0.f, 0.f}, {0.f, 0.f}};
        const float4* bwp = (const float4*)(bw + ol * HDIM + hb + tig * 2);
        #pragma unroll
        for (int n = 0; n < 8; ++n) {
            float4 q = bwp[n * 4];   // (0.5*b1[h0], w2[h0], 0.5*b1[h1], w2[h1])
            #pragma unroll
            for (int t = 0; t < 2; ++t) {
                float h00 = fmaf(c[t][n][0], 0.5f, q.x);
                float h01 = fmaf(c[t][n][1], 0.5f, q.z);
                float h10 = fmaf(c[t][n][2], 0.5f, q.x);
                float h11 = fmaf(c[t][n][3], 0.5f, q.z);
                acc[t][0] = fmaf(fmaf(h00, tanh_ap(h00), h00), q.y, acc[t][0]);
                acc[t][0] = fmaf(fmaf(h01, tanh_ap(h01), h01), q.w, acc[t][0]);
                acc[t][1] = fmaf(fmaf(h10, tanh_ap(h10), h10), q.y, acc[t][1]);
                acc[t][1] = fmaf(fmaf(h11, tanh_ap(h11), h11), q.w, acc[t][1]);
            }
        }

        #pragma unroll
        for (int t = 0; t < 2; ++t)
            #pragma unroll
            for (int r = 0; r < 2; ++r) {
                float v = acc[t][r];
                v += __shfl_xor_sync(0xffffffffu, v, 1);
                v += __shfl_xor_sync(0xffffffffu, v, 2);
                if (tig == 0)
                    part[(ol * 2 + cg) * 256 + rw + t * 16 + r * 8 + gid] = v;
            }
    }

    __syncthreads();

    // ---- combine cg partials, add b2, coalesced float4 store ----
    if (tid < 256) {
        float4 o;
        float* po = (float*)&o;
        #pragma unroll
        for (int ol = 0; ol < OPB; ++ol)
            po[ol] = part[(ol * 2) * 256 + tid] + part[(ol * 2 + 1) * 256 + tid]
                   + __ldg(b2 + o0 + ol);
        *(float4*)(out + (size_t)(R0 + tid) * ODIM + o0) = o;
    }
}

extern "C" void kernel_launch(void* const* d_in, const int* in_sizes, int n_in,
                              void* d_out, int out_size)
{
    const float* x  = (const float*)d_in[0];  // [NC, 64]
    const float* W1 = (const float*)d_in[1];  // [32, 128, 64]
    const float* b1 = (const float*)d_in[2];  // [32, 128]
    const float* W2 = (const float*)d_in[3];  // [32, 128]
    const float* b2 = (const float*)d_in[4];  // [32]
    float* out = (float*)d_out;               // [NC, 32]

    const int NC = in_sizes[0] / KDIM;        // 131072

    cudaFuncSetAttribute(swr_kernel, cudaFuncAttributeMaxDynamicSharedMemorySize, SMEM_BYTES);

    dim3 grid(NC / ROWS, ODIM / OPB);         // (512, 8)
    swr_kernel<<<grid, THREADS, SMEM_BYTES>>>(x, W1, b1, W2, b2, out);
}